// round 1
// baseline (speedup 1.0000x reference)
#include <cuda_runtime.h>
#include <stdint.h>
#include <math.h>

#define BATCH 64
#define SEQ   256
#define DIM   1024
#define NPROMPT 512
#define BETA_C 0.75f
#define TEMP_C 0.1f

// ---------------- device scratch (static globals; no allocation) ----------------
__device__ float g_i[BATCH * DIM];      // ema_concept (selected)
__device__ float g_iCi[BATCH * DIM];    // i @ C_inv
__device__ float g_co[BATCH * DIM];     // i @ W^T
__device__ float g_E[BATCH];            // i_energy
__device__ float g_simn[BATCH * SEQ];   // sim / E
__device__ float g_sig[BATCH * SEQ];    // sigmoid((sim/E - beta)/T)
__device__ float g_Wt[DIM * DIM];       // weight transposed: Wt[k][o] = W[o][k]

// ---------------- K0: transpose weight (needed for coalesced co GEMM) -----------
__global__ void k_transpose(const float* __restrict__ W) {
    __shared__ float t[32][33];
    int x = blockIdx.x * 32 + threadIdx.x;
    int y0 = blockIdx.y * 32;
#pragma unroll
    for (int j = 0; j < 32; j += 8)
        t[threadIdx.y + j][threadIdx.x] = W[(size_t)(y0 + threadIdx.y + j) * DIM + x];
    __syncthreads();
    int x2 = blockIdx.y * 32 + threadIdx.x;
    int y2 = blockIdx.x * 32;
#pragma unroll
    for (int j = 0; j < 32; j += 8)
        g_Wt[(size_t)(y2 + threadIdx.y + j) * DIM + x2] = t[threadIdx.x][threadIdx.y + j];
}

// ---------------- K1: gather i[b,:] = initted ? ema_table[pid] : text_enc[b,ci] --
__global__ void k_gather(const int* __restrict__ prompt_ids,
                         const int* __restrict__ concept_indices,
                         const uint8_t* __restrict__ initted,
                         const float* __restrict__ ema_table,
                         const float* __restrict__ text_enc) {
    int b = blockIdx.x;
    int pid = prompt_ids[b];
    int ci = concept_indices[b];
    bool init = initted[pid] != 0;
    const float* src = init ? (ema_table + (size_t)pid * DIM)
                            : (text_enc + ((size_t)b * SEQ + ci) * DIM);
    for (int d = threadIdx.x; d < DIM; d += blockDim.x)
        g_i[b * DIM + d] = src[d];
}

// ---------------- K2: small GEMMs  out[b,d] = sum_k i[b,k] * M[k,d] -------------
// z==0: M = C_inv -> g_iCi ; z==1: M = Wt -> g_co
__global__ void k_smallgemm(const float* __restrict__ Cinv) {
    const float* __restrict__ M = (blockIdx.z == 0) ? Cinv : g_Wt;
    float* __restrict__ out = (blockIdx.z == 0) ? g_iCi : g_co;
    int d = blockIdx.x * 128 + threadIdx.x;
    int b0 = blockIdx.y * 8;
    __shared__ float ish[8][128];
    float acc[8];
#pragma unroll
    for (int r = 0; r < 8; r++) acc[r] = 0.0f;

    for (int k0 = 0; k0 < DIM; k0 += 128) {
#pragma unroll
        for (int r = 0; r < 8; r++)
            ish[r][threadIdx.x] = g_i[(b0 + r) * DIM + k0 + threadIdx.x];
        __syncthreads();
#pragma unroll 4
        for (int kk = 0; kk < 128; kk++) {
            float m = M[(size_t)(k0 + kk) * DIM + d];
#pragma unroll
            for (int r = 0; r < 8; r++) acc[r] += ish[r][kk] * m;
        }
        __syncthreads();
    }
#pragma unroll
    for (int r = 0; r < 8; r++) out[(b0 + r) * DIM + d] = acc[r];
}

// ---------------- K3: i_energy[b] = sum_d iCi[b,d] * i[b,d] ---------------------
__global__ void k_energy() {
    int b = blockIdx.x, tid = threadIdx.x;
    float s = 0.0f;
    for (int d = tid; d < DIM; d += 256)
        s += g_iCi[b * DIM + d] * g_i[b * DIM + d];
#pragma unroll
    for (int o = 16; o; o >>= 1) s += __shfl_xor_sync(0xffffffffu, s, o);
    __shared__ float red[8];
    if ((tid & 31) == 0) red[tid >> 5] = s;
    __syncthreads();
    if (tid < 8) {
        float t = red[tid];
#pragma unroll
        for (int o = 4; o; o >>= 1) t += __shfl_xor_sync(0xffu, t, o);
        if (tid == 0) g_E[b] = t;
    }
}

// ---------------- K4: sim/E and sigmoid term, one warp per (b,n) row -------------
__global__ void k_sim(const float* __restrict__ text_enc) {
    int warp = threadIdx.x >> 5, lane = threadIdx.x & 31;
    int m = blockIdx.x * 8 + warp;          // m = b*SEQ + n, 0..16383
    int b = m >> 8;
    const float4* x = (const float4*)(text_enc + (size_t)m * DIM);
    const float4* c = (const float4*)(g_iCi + (size_t)b * DIM);
    float s = 0.0f;
#pragma unroll
    for (int it = 0; it < 8; it++) {
        int idx = it * 32 + lane;
        float4 xv = x[idx], cv = c[idx];
        s += xv.x * cv.x + xv.y * cv.y + xv.z * cv.z + xv.w * cv.w;
    }
#pragma unroll
    for (int o = 16; o; o >>= 1) s += __shfl_xor_sync(0xffffffffu, s, o);
    if (lane == 0) {
        float simn = s / g_E[b];
        g_simn[m] = simn;
        g_sig[m] = 1.0f / (1.0f + expf(-(simn - BETA_C) / TEMP_C));
    }
}

// ---------------- K5: main GEMM (16384x1024x1024) with fused epilogue ------------
// C[m,o] = sum_k A[m,k]*W[o,k];  out = C - simn[m]*co[b,o] + sig[m]*outs
__global__ __launch_bounds__(256) void k_main(
    const float* __restrict__ A,             // text_enc [16384][1024]
    const float* __restrict__ W,             // weight [1024][1024] (o-major)
    const int* __restrict__ prompt_ids,
    const uint8_t* __restrict__ initted,
    const float* __restrict__ outputs_table, // [512][256][1024]
    float* __restrict__ out)
{
    __shared__ __align__(16) float As[2][16][132];
    __shared__ __align__(16) float Bs[2][16][132];

    int tid = threadIdx.x;
    int tx = tid & 15, ty = tid >> 4;
    int m0 = blockIdx.y * 128;
    int n0 = blockIdx.x * 128;

    // global-load mapping: thread loads rows r0 and r0+64, cols kc0..kc0+3 of the tile
    int r0 = tid >> 2;
    int kc0 = (tid & 3) * 4;

    const float* Abase0 = A + (size_t)(m0 + r0) * DIM + kc0;
    const float* Abase1 = A + (size_t)(m0 + r0 + 64) * DIM + kc0;
    const float* Bbase0 = W + (size_t)(n0 + r0) * DIM + kc0;
    const float* Bbase1 = W + (size_t)(n0 + r0 + 64) * DIM + kc0;

    float4 a0, a1, b0, b1;

    // prologue: tile 0
    a0 = *(const float4*)(Abase0);
    a1 = *(const float4*)(Abase1);
    b0 = *(const float4*)(Bbase0);
    b1 = *(const float4*)(Bbase1);
    {
        As[0][kc0 + 0][r0] = a0.x; As[0][kc0 + 1][r0] = a0.y; As[0][kc0 + 2][r0] = a0.z; As[0][kc0 + 3][r0] = a0.w;
        As[0][kc0 + 0][r0 + 64] = a1.x; As[0][kc0 + 1][r0 + 64] = a1.y; As[0][kc0 + 2][r0 + 64] = a1.z; As[0][kc0 + 3][r0 + 64] = a1.w;
        Bs[0][kc0 + 0][r0] = b0.x; Bs[0][kc0 + 1][r0] = b0.y; Bs[0][kc0 + 2][r0] = b0.z; Bs[0][kc0 + 3][r0] = b0.w;
        Bs[0][kc0 + 0][r0 + 64] = b1.x; Bs[0][kc0 + 1][r0 + 64] = b1.y; Bs[0][kc0 + 2][r0 + 64] = b1.z; Bs[0][kc0 + 3][r0 + 64] = b1.w;
    }
    __syncthreads();

    float acc[8][8];
#pragma unroll
    for (int i = 0; i < 8; i++)
#pragma unroll
        for (int j = 0; j < 8; j++) acc[i][j] = 0.0f;

    float Am[8], Bn[8];

    const int NKT = DIM / 16;   // 64 k-tiles
    for (int kt = 0; kt < NKT; kt++) {
        int cur = kt & 1;
        if (kt < NKT - 1) {
            int k1 = (kt + 1) * 16;
            a0 = *(const float4*)(Abase0 + k1);
            a1 = *(const float4*)(Abase1 + k1);
            b0 = *(const float4*)(Bbase0 + k1);
            b1 = *(const float4*)(Bbase1 + k1);
        }
#pragma unroll
        for (int kk = 0; kk < 16; kk++) {
            *(float4*)&Am[0] = *(const float4*)&As[cur][kk][ty * 4];
            *(float4*)&Am[4] = *(const float4*)&As[cur][kk][ty * 4 + 64];
            *(float4*)&Bn[0] = *(const float4*)&Bs[cur][kk][tx * 4];
            *(float4*)&Bn[4] = *(const float4*)&Bs[cur][kk][tx * 4 + 64];
#pragma unroll
            for (int i = 0; i < 8; i++)
#pragma unroll
                for (int j = 0; j < 8; j++)
                    acc[i][j] += Am[i] * Bn[j];
        }
        if (kt < NKT - 1) {
            int nxt = cur ^ 1;
            As[nxt][kc0 + 0][r0] = a0.x; As[nxt][kc0 + 1][r0] = a0.y; As[nxt][kc0 + 2][r0] = a0.z; As[nxt][kc0 + 3][r0] = a0.w;
            As[nxt][kc0 + 0][r0 + 64] = a1.x; As[nxt][kc0 + 1][r0 + 64] = a1.y; As[nxt][kc0 + 2][r0 + 64] = a1.z; As[nxt][kc0 + 3][r0 + 64] = a1.w;
            Bs[nxt][kc0 + 0][r0] = b0.x; Bs[nxt][kc0 + 1][r0] = b0.y; Bs[nxt][kc0 + 2][r0] = b0.z; Bs[nxt][kc0 + 3][r0] = b0.w;
            Bs[nxt][kc0 + 0][r0 + 64] = b1.x; Bs[nxt][kc0 + 1][r0 + 64] = b1.y; Bs[nxt][kc0 + 2][r0 + 64] = b1.z; Bs[nxt][kc0 + 3][r0 + 64] = b1.w;
            __syncthreads();
        }
    }

    // ---- fused epilogue ----
    int b = m0 >> 8;                 // 128-row tile lies entirely within one batch
    int pid = prompt_ids[b];
    bool init = initted[pid] != 0;

    float coreg[8];
#pragma unroll
    for (int j = 0; j < 8; j++) {
        int col = n0 + ((j < 4) ? (tx * 4 + j) : (64 + tx * 4 + (j - 4)));
        coreg[j] = g_co[b * DIM + col];
    }

#pragma unroll
    for (int i = 0; i < 8; i++) {
        int rl = (i < 4) ? (ty * 4 + i) : (64 + ty * 4 + (i - 4));
        int m = m0 + rl;
        float simn = g_simn[m];
        float sig = g_sig[m];
        int n = m & (SEQ - 1);
#pragma unroll
        for (int cg = 0; cg < 2; cg++) {
            int cbase = n0 + cg * 64 + tx * 4;
            float4 v;
            float* vp = (float*)&v;
#pragma unroll
            for (int j = 0; j < 4; j++) {
                float orig = acc[i][cg * 4 + j];
                float osel = init ? outputs_table[((size_t)pid * SEQ + n) * DIM + cbase + j]
                                  : orig;
                vp[j] = orig - simn * coreg[cg * 4 + j] + sig * osel;
            }
            *(float4*)&out[(size_t)m * DIM + cbase] = v;
        }
    }
}

// --------------------------------- launch ---------------------------------------
extern "C" void kernel_launch(void* const* d_in, const int* in_sizes, int n_in,
                              void* d_out, int out_size) {
    const int*     prompt_ids      = (const int*)d_in[0];
    const float*   text_enc        = (const float*)d_in[1];
    const int*     concept_indices = (const int*)d_in[2];
    const float*   weight          = (const float*)d_in[3];
    const float*   C_inv           = (const float*)d_in[4];
    const uint8_t* initted         = (const uint8_t*)d_in[5];
    const float*   ema_table       = (const float*)d_in[6];
    const float*   outputs_table   = (const float*)d_in[7];
    float*         out             = (float*)d_out;

    (void)in_sizes; (void)n_in; (void)out_size;

    k_transpose<<<dim3(DIM / 32, DIM / 32), dim3(32, 8)>>>(weight);
    k_gather<<<BATCH, 256>>>(prompt_ids, concept_indices, initted, ema_table, text_enc);
    k_smallgemm<<<dim3(DIM / 128, BATCH / 8, 2), 128>>>(C_inv);
    k_energy<<<BATCH, 256>>>();
    k_sim<<<(BATCH * SEQ) / 8, 256>>>(text_enc);
    k_main<<<dim3(DIM / 128, (BATCH * SEQ) / 128), 256>>>(
        text_enc, weight, prompt_ids, initted, outputs_table, out);
}

// round 3
// speedup vs baseline: 1.2210x; 1.2210x over previous
#include <cuda_runtime.h>
#include <stdint.h>
#include <math.h>

#define BATCH 64
#define SEQ   256
#define DIM   1024
#define BETA_C 0.75f
#define TEMP_C 0.1f

// ---- GEMM tiling ----
#define BM 128
#define BN 128
#define BK 32
#define NKT (DIM / BK)              // 32 k-chunks
#define STAGE_FLOATS 8192           // A frags 4096 + B frags 4096
#define SMEM_TOTAL (2 * STAGE_FLOATS * 4)   // 64 KB

// ---------------- device scratch ----------------
__device__ float g_i[BATCH * DIM];
__device__ float g_iCi[BATCH * DIM];
__device__ float g_co[BATCH * DIM];
__device__ float g_E[BATCH];
__device__ float g_simn[BATCH * SEQ];
__device__ float g_sig[BATCH * SEQ];
__device__ float g_Wt[DIM * DIM];

// ---------------- K0: transpose weight ----------------
__global__ void k_transpose(const float* __restrict__ W) {
    __shared__ float t[32][33];
    int x = blockIdx.x * 32 + threadIdx.x;
    int y0 = blockIdx.y * 32;
#pragma unroll
    for (int j = 0; j < 32; j += 8)
        t[threadIdx.y + j][threadIdx.x] = W[(size_t)(y0 + threadIdx.y + j) * DIM + x];
    __syncthreads();
    int x2 = blockIdx.y * 32 + threadIdx.x;
    int y2 = blockIdx.x * 32;
#pragma unroll
    for (int j = 0; j < 32; j += 8)
        g_Wt[(size_t)(y2 + threadIdx.y + j) * DIM + x2] = t[threadIdx.x][threadIdx.y + j];
}

// ---------------- K1: gather i ----------------
__global__ void k_gather(const int* __restrict__ prompt_ids,
                         const int* __restrict__ concept_indices,
                         const uint8_t* __restrict__ initted,
                         const float* __restrict__ ema_table,
                         const float* __restrict__ text_enc) {
    int b = blockIdx.x;
    int pid = prompt_ids[b];
    int ci = concept_indices[b];
    bool init = initted[pid] != 0;
    const float* src = init ? (ema_table + (size_t)pid * DIM)
                            : (text_enc + ((size_t)b * SEQ + ci) * DIM);
    for (int d = threadIdx.x; d < DIM; d += blockDim.x)
        g_i[b * DIM + d] = src[d];
}

// ---------------- K2: small GEMMs ----------------
__global__ void k_smallgemm(const float* __restrict__ Cinv) {
    const float* __restrict__ M = (blockIdx.z == 0) ? Cinv : g_Wt;
    float* __restrict__ out = (blockIdx.z == 0) ? g_iCi : g_co;
    int d = blockIdx.x * 128 + threadIdx.x;
    int b0 = blockIdx.y * 8;
    __shared__ float ish[8][128];
    float acc[8];
#pragma unroll
    for (int r = 0; r < 8; r++) acc[r] = 0.0f;
    for (int k0 = 0; k0 < DIM; k0 += 128) {
#pragma unroll
        for (int r = 0; r < 8; r++)
            ish[r][threadIdx.x] = g_i[(b0 + r) * DIM + k0 + threadIdx.x];
        __syncthreads();
#pragma unroll 4
        for (int kk = 0; kk < 128; kk++) {
            float m = M[(size_t)(k0 + kk) * DIM + d];
#pragma unroll
            for (int r = 0; r < 8; r++) acc[r] += ish[r][kk] * m;
        }
        __syncthreads();
    }
#pragma unroll
    for (int r = 0; r < 8; r++) out[(b0 + r) * DIM + d] = acc[r];
}

// ---------------- K3: i_energy ----------------
__global__ void k_energy() {
    int b = blockIdx.x, tid = threadIdx.x;
    float s = 0.0f;
    for (int d = tid; d < DIM; d += 256)
        s += g_iCi[b * DIM + d] * g_i[b * DIM + d];
#pragma unroll
    for (int o = 16; o; o >>= 1) s += __shfl_xor_sync(0xffffffffu, s, o);
    __shared__ float red[8];
    if ((tid & 31) == 0) red[tid >> 5] = s;
    __syncthreads();
    if (tid < 8) {
        float t = red[tid];
#pragma unroll
        for (int o = 4; o; o >>= 1) t += __shfl_xor_sync(0xffu, t, o);
        if (tid == 0) g_E[b] = t;
    }
}

// ---------------- K4: sim + sigmoid ----------------
__global__ void k_sim(const float* __restrict__ text_enc) {
    int warp = threadIdx.x >> 5, lane = threadIdx.x & 31;
    int m = blockIdx.x * 8 + warp;
    int b = m >> 8;
    const float4* x = (const float4*)(text_enc + (size_t)m * DIM);
    const float4* c = (const float4*)(g_iCi + (size_t)b * DIM);
    float s = 0.0f;
#pragma unroll
    for (int it = 0; it < 8; it++) {
        int idx = it * 32 + lane;
        float4 xv = x[idx], cv = c[idx];
        s += xv.x * cv.x + xv.y * cv.y + xv.z * cv.z + xv.w * cv.w;
    }
#pragma unroll
    for (int o = 16; o; o >>= 1) s += __shfl_xor_sync(0xffffffffu, s, o);
    if (lane == 0) {
        float simn = s / g_E[b];
        g_simn[m] = simn;
        g_sig[m] = 1.0f / (1.0f + expf(-(simn - BETA_C) / TEMP_C));
    }
}

// ---------------- tf32 helpers ----------------
__device__ __forceinline__ uint32_t f2tf32(float x) {
    uint32_t r;
    asm("cvt.rna.tf32.f32 %0, %1;" : "=r"(r) : "f"(x));
    return r;
}
__device__ __forceinline__ void mma_tf32(float* c, const uint4& a, const uint2& b) {
    asm volatile(
        "mma.sync.aligned.m16n8k8.row.col.f32.tf32.tf32.f32 "
        "{%0,%1,%2,%3}, {%4,%5,%6,%7}, {%8,%9}, {%0,%1,%2,%3};"
        : "+f"(c[0]), "+f"(c[1]), "+f"(c[2]), "+f"(c[3])
        : "r"(a.x), "r"(a.y), "r"(a.z), "r"(a.w), "r"(b.x), "r"(b.y));
}

// Store one float4 (4 consecutive k) of A into fragment layout.
// A elem (m,k): ks=k>>3, krh=(k>>2)&1, lane=((m&7)<<2)|(k&3), reg=((m>>3)&1)|(krh<<1)
__device__ __forceinline__ void sts_fragA(float* base, int mrow, int k0, const float4 v) {
    int ks = k0 >> 3, krh = (k0 >> 2) & 1;
    int mt = mrow >> 4, mr = mrow & 15;
    float* p = base + (((ks * 8 + mt) * 32 + ((mr & 7) << 2)) << 2) + ((mr >> 3) | (krh << 1));
    p[0] = v.x; p[4] = v.y; p[8] = v.z; p[12] = v.w;
}
// B elem (n,k): lane=((n&7)<<2)|(k&3), reg=krh
__device__ __forceinline__ void sts_fragB(float* base, int nrow, int k0, const float4 v) {
    int ks = k0 >> 3, krh = (k0 >> 2) & 1;
    int nt = nrow >> 3, nr = nrow & 7;
    float* p = base + 4096 + (((ks * 16 + nt) * 32 + (nr << 2)) << 1) + krh;
    p[0] = v.x; p[2] = v.y; p[4] = v.z; p[6] = v.w;
}

// ---------------- K5: tf32 mma.sync GEMM + fused epilogue ----------------
__global__ __launch_bounds__(256) void k_main(
    const float* __restrict__ A,              // text_enc [16384][1024]
    const float* __restrict__ W,              // weight   [1024][1024]
    const int* __restrict__ prompt_ids,
    const uint8_t* __restrict__ initted,
    const float* __restrict__ outputs_table,  // [512][256][1024]
    float* __restrict__ out) {
    extern __shared__ float sf[];

    const int tid = threadIdx.x;
    const int wid = tid >> 5, lane = tid & 31;
    const int wm = wid & 1, wn = wid >> 1;     // warp tile: rows 64*wm, cols 32*wn
    const int m0 = blockIdx.y * BM;
    const int n0 = blockIdx.x * BN;

    // producer mapping: each thread handles one row pair-half
    const int prow = tid >> 1;                 // 0..127
    const int pk = (tid & 1) * 16;             // 0 or 16
    const float* Aptr = A + (size_t)(m0 + prow) * DIM + pk;
    const float* Bptr = W + (size_t)(n0 + prow) * DIM + pk;

    float acc[4][4][4];
#pragma unroll
    for (int i = 0; i < 4; i++)
#pragma unroll
        for (int j = 0; j < 4; j++)
#pragma unroll
            for (int r = 0; r < 4; r++) acc[i][j][r] = 0.0f;

    float4 pa[4], pb[4];
    // prologue: chunk 0 -> stage 0
#pragma unroll
    for (int u = 0; u < 4; u++) {
        pa[u] = *(const float4*)(Aptr + u * 4);
        pb[u] = *(const float4*)(Bptr + u * 4);
    }
#pragma unroll
    for (int u = 0; u < 4; u++) {
        float4 ta = make_float4(__uint_as_float(f2tf32(pa[u].x)), __uint_as_float(f2tf32(pa[u].y)),
                                __uint_as_float(f2tf32(pa[u].z)), __uint_as_float(f2tf32(pa[u].w)));
        float4 tb = make_float4(__uint_as_float(f2tf32(pb[u].x)), __uint_as_float(f2tf32(pb[u].y)),
                                __uint_as_float(f2tf32(pb[u].z)), __uint_as_float(f2tf32(pb[u].w)));
        sts_fragA(sf, prow, pk + u * 4, ta);
        sts_fragB(sf, prow, pk + u * 4, tb);
    }
    __syncthreads();

    for (int kt = 0; kt < NKT; kt++) {
        float* cur = sf + (kt & 1) * STAGE_FLOATS;
        if (kt + 1 < NKT) {
            const float* Ap = Aptr + (kt + 1) * BK;
            const float* Bp = Bptr + (kt + 1) * BK;
#pragma unroll
            for (int u = 0; u < 4; u++) {
                pa[u] = *(const float4*)(Ap + u * 4);
                pb[u] = *(const float4*)(Bp + u * 4);
            }
        }
        // compute on current stage: 4 k8-steps
#pragma unroll
        for (int ks = 0; ks < 4; ks++) {
            uint4 afr[4];
            uint2 bfr[4];
#pragma unroll
            for (int i = 0; i < 4; i++)
                afr[i] = *(const uint4*)(cur + (((ks * 8 + wm * 4 + i) * 32 + lane) << 2));
#pragma unroll
            for (int j = 0; j < 4; j++)
                bfr[j] = *(const uint2*)(cur + 4096 + (((ks * 16 + wn * 4 + j) * 32 + lane) << 1));
#pragma unroll
            for (int i = 0; i < 4; i++)
#pragma unroll
                for (int j = 0; j < 4; j++)
                    mma_tf32(acc[i][j], afr[i], bfr[j]);
        }
        if (kt + 1 < NKT) {
            __syncthreads();
            float* nxt = sf + ((kt + 1) & 1) * STAGE_FLOATS;
#pragma unroll
            for (int u = 0; u < 4; u++) {
                float4 ta = make_float4(__uint_as_float(f2tf32(pa[u].x)), __uint_as_float(f2tf32(pa[u].y)),
                                        __uint_as_float(f2tf32(pa[u].z)), __uint_as_float(f2tf32(pa[u].w)));
                float4 tb = make_float4(__uint_as_float(f2tf32(pb[u].x)), __uint_as_float(f2tf32(pb[u].y)),
                                        __uint_as_float(f2tf32(pb[u].z)), __uint_as_float(f2tf32(pb[u].w)));
                sts_fragA(nxt, prow, pk + u * 4, ta);
                sts_fragB(nxt, prow, pk + u * 4, tb);
            }
            __syncthreads();
        }
    }

    // ---------------- fused epilogue ----------------
    const int b = m0 >> 8;
    const int pid = prompt_ids[b];
    const bool init = initted[pid] != 0;

    float2 co2[4];
#pragma unroll
    for (int j = 0; j < 4; j++)
        co2[j] = *(const float2*)&g_co[b * DIM + n0 + wn * 32 + j * 8 + (lane & 3) * 2];

#pragma unroll
    for (int i = 0; i < 4; i++) {
        int gr0 = m0 + wm * 64 + i * 16 + (lane >> 2);
        int gr1 = gr0 + 8;
        float simn0 = g_simn[gr0], sig0 = g_sig[gr0];
        float simn1 = g_simn[gr1], sig1 = g_sig[gr1];
        const float* ot0 = outputs_table + ((size_t)pid * SEQ + (gr0 & (SEQ - 1))) * DIM;
        const float* ot1 = outputs_table + ((size_t)pid * SEQ + (gr1 & (SEQ - 1))) * DIM;
#pragma unroll
        for (int j = 0; j < 4; j++) {
            int col = n0 + wn * 32 + j * 8 + (lane & 3) * 2;
            float c0 = acc[i][j][0], c1 = acc[i][j][1];
            float c2 = acc[i][j][2], c3 = acc[i][j][3];
            float o0 = init ? ot0[col] : c0;
            float o1 = init ? ot0[col + 1] : c1;
            float o2 = init ? ot1[col] : c2;
            float o3 = init ? ot1[col + 1] : c3;
            float2 v0 = make_float2(c0 - simn0 * co2[j].x + sig0 * o0,
                                    c1 - simn0 * co2[j].y + sig0 * o1);
            float2 v1 = make_float2(c2 - simn1 * co2[j].x + sig1 * o2,
                                    c3 - simn1 * co2[j].y + sig1 * o3);
            *(float2*)&out[(size_t)gr0 * DIM + col] = v0;
            *(float2*)&out[(size_t)gr1 * DIM + col] = v1;
        }
    }
}

// --------------------------------- launch ---------------------------------------
extern "C" void kernel_launch(void* const* d_in, const int* in_sizes, int n_in,
                              void* d_out, int out_size) {
    const int*     prompt_ids      = (const int*)d_in[0];
    const float*   text_enc        = (const float*)d_in[1];
    const int*     concept_indices = (const int*)d_in[2];
    const float*   weight          = (const float*)d_in[3];
    const float*   C_inv           = (const float*)d_in[4];
    const uint8_t* initted         = (const uint8_t*)d_in[5];
    const float*   ema_table       = (const float*)d_in[6];
    const float*   outputs_table   = (const float*)d_in[7];
    float*         out             = (float*)d_out;

    (void)in_sizes; (void)n_in; (void)out_size;

    cudaFuncSetAttribute(k_main, cudaFuncAttributeMaxDynamicSharedMemorySize, SMEM_TOTAL);

    k_transpose<<<dim3(DIM / 32, DIM / 32), dim3(32, 8)>>>(weight);
    k_gather<<<BATCH, 256>>>(prompt_ids, concept_indices, initted, ema_table, text_enc);
    k_smallgemm<<<dim3(DIM / 128, BATCH / 8, 2), 128>>>(C_inv);
    k_energy<<<BATCH, 256>>>();
    k_sim<<<(BATCH * SEQ) / 8, 256>>>(text_enc);
    k_main<<<dim3(DIM / BN, (BATCH * SEQ) / BM), 256, SMEM_TOTAL>>>(
        text_enc, weight, prompt_ids, initted, outputs_table, out);
}